// round 10
// baseline (speedup 1.0000x reference)
#include <cuda_runtime.h>
#include <cuda_bf16.h>
#include <cuda_fp16.h>
#include <stdint.h>

#define N_NODES 100000
#define N_EDGES 1600000
#define D_IN    256
#define D_OUT   128
#define N_TILES ((N_NODES + 127) / 128)   // 782

// ---------------- device scratch (no allocations allowed) ----------------
// support stored as fp16, packed half2 in u32: [N_NODES][64] u32
__device__ uint32_t g_support_h[(size_t)N_NODES * (D_OUT / 2)];   // 25.6 MB
__device__ int   g_counts[N_NODES];
__device__ int   g_rowptr[N_NODES + 1];
__device__ int   g_cursor[N_NODES];
__device__ int2  g_sorted_cv[N_EDGES];                 // (col, val-bits) sorted by row

#define SCAN_B 1024
#define NSB    ((N_NODES + SCAN_B - 1) / SCAN_B)       // 98
__device__ int   g_blocksums[NSB];

// ---------------- 1) HMMA GEMM: support = X @ W, N-split 2 CTAs/SM -------
// Each CTA computes a 128x64 half-tile. SMEM:
//   w_s: 64 cols x 264 u32  (hi pairs [0..127], lo pairs [128..255], pad 8)
//   a_s: 2 stages x 128 rows x 40 u32 (hi interleaved [0..15], lo [16..31], pad 8)
// k-pair interleave: within each 16-pair block, pair p (q=p&7, kk=p>>3) sits at
// pos = kk*8 + 2*(q&3) + (q>>2)  ->  fragment pairs (c, c+4) are ADJACENT -> LDS.64.
#define WS   264
#define AST  40
#define W_U32   (64 * WS)                 // 16896
#define A_U32S  (128 * AST)               // 5120
#define SM_TOTAL_B ((W_U32 + 2 * A_U32S) * 4)   // 108544 bytes

// pack two fp32 -> bf16x2 (f0 low half, f1 high half)
__device__ __forceinline__ uint32_t pack_bf(float f0, float f1) {
    uint32_t r;
    asm("cvt.rn.bf16x2.f32 %0, %1, %2;" : "=r"(r) : "f"(f1), "f"(f0));
    return r;
}
// split a packed bf16x2 pair: return lo-residual pair for (f0, f1) vs hq
__device__ __forceinline__ uint32_t lo_bf(uint32_t hq, float f0, float f1) {
    float h0 = __uint_as_float(hq << 16);
    float h1 = __uint_as_float(hq & 0xFFFF0000u);
    return pack_bf(f0 - h0, f1 - h1);
}

__device__ __forceinline__ void mma16816(float* d, const uint32_t* a, const uint32_t* b) {
    asm volatile(
        "mma.sync.aligned.m16n8k16.row.col.f32.bf16.bf16.f32 "
        "{%0,%1,%2,%3}, {%4,%5,%6,%7}, {%8,%9}, {%0,%1,%2,%3};"
        : "+f"(d[0]), "+f"(d[1]), "+f"(d[2]), "+f"(d[3])
        : "r"(a[0]), "r"(a[1]), "r"(a[2]), "r"(a[3]), "r"(b[0]), "r"(b[1]));
}

__global__ __launch_bounds__(256, 2)
void gemm_mma_kernel(const float* __restrict__ A, const float* __restrict__ W) {
    extern __shared__ uint32_t smem[];
    uint32_t* w_s = smem;                 // [64][WS]
    uint32_t* a_s = smem + W_U32;         // [2][128][AST]

    const int tid    = threadIdx.x;
    const int wid    = tid >> 5;          // 0..7
    const int lane   = tid & 31;
    const int warp_m = wid & 3;           // 4 row-bands of 32
    const int warp_n = wid >> 2;          // 2 col-bands of 32 (within 64-col half)
    const int g      = lane >> 2;
    const int c      = lane & 3;
    const int half   = blockIdx.x & 1;    // which 64-col half of W

    // ---- W prologue: split fp32 W -> bf16 hi/lo, interleaved, SMEM ----
    for (int idx = tid; idx < 64 * 128; idx += 256) {
        const int p  = idx >> 6;          // global k-pair 0..127
        const int n1 = idx & 63;          // local col
        const int n  = half * 64 + n1;
        const float w0 = W[(size_t)(2 * p) * D_OUT + n];
        const float w1 = W[(size_t)(2 * p + 1) * D_OUT + n];
        const uint32_t hq = pack_bf(w0, w1);
        const uint32_t lq = lo_bf(hq, w0, w1);
        const int q16 = p & 15, kk = q16 >> 3, q = q16 & 7;
        const int pos = (p >> 4) * 16 + kk * 8 + 2 * (q & 3) + (q >> 2);
        w_s[n1 * WS + pos]       = hq;
        w_s[n1 * WS + 128 + pos] = lq;
    }
    __syncthreads();

    // A loader mapping: thread handles rows rb and rb+64, quarter a_q.
    // Thread owns pairs {a_q, a_q+4, a_q+8, a_q+12} of each 16-pair block
    // -> interleaved positions (2a_q, 2a_q+1) and (8+2a_q, 9+2a_q) -> STS.64.
    const int rb  = tid >> 2;             // 0..63
    const int a_q = tid & 3;

    // ---- register prefetch (depth 1): 2 rows x 4 float2 ----
    float2 pf[2][4];
    {
        const int t0 = blockIdx.x >> 1;
#pragma unroll
        for (int rr = 0; rr < 2; rr++) {
            const int gr = t0 * 128 + rb + rr * 64;
            if (t0 < N_TILES && gr < N_NODES) {
                const float2* p = (const float2*)(A + (size_t)gr * D_IN) + a_q;
#pragma unroll
                for (int j = 0; j < 4; j++) pf[rr][j] = p[j * 4];
            } else {
#pragma unroll
                for (int j = 0; j < 4; j++) pf[rr][j] = make_float2(0.f, 0.f);
            }
        }
    }

    for (int tile = blockIdx.x >> 1; tile < N_TILES; tile += 148) {
        const int m0 = tile * 128;

        float acc[2][4][4];
#pragma unroll
        for (int mt = 0; mt < 2; mt++)
#pragma unroll
            for (int nt = 0; nt < 4; nt++)
#pragma unroll
                for (int q = 0; q < 4; q++) acc[mt][nt][q] = 0.f;

        for (int kb = 0; kb < 8; kb++) {
            const int st = kb & 1;
            uint32_t* as = a_s + st * A_U32S;

            // ---- convert prefetched regs + store interleaved (STS.64) ----
#pragma unroll
            for (int rr = 0; rr < 2; rr++) {
                const int row = rb + rr * 64;
                uint32_t hq[4], lq[4];
#pragma unroll
                for (int j = 0; j < 4; j++) {
                    hq[j] = pack_bf(pf[rr][j].x, pf[rr][j].y);
                    lq[j] = lo_bf(hq[j], pf[rr][j].x, pf[rr][j].y);
                }
                uint32_t* d = as + row * AST;
                *(uint2*)(d + 2 * a_q)          = make_uint2(hq[0], hq[1]);
                *(uint2*)(d + 8 + 2 * a_q)      = make_uint2(hq[2], hq[3]);
                *(uint2*)(d + 16 + 2 * a_q)     = make_uint2(lq[0], lq[1]);
                *(uint2*)(d + 16 + 8 + 2 * a_q) = make_uint2(lq[2], lq[3]);
            }

            // ---- issue prefetch for next k-block (or next tile) ----
            {
                int nkb = kb + 1, ntile = tile;
                if (nkb == 8) { nkb = 0; ntile = tile + 148; }
#pragma unroll
                for (int rr = 0; rr < 2; rr++) {
                    const int gr = ntile * 128 + rb + rr * 64;
                    if (ntile < N_TILES && gr < N_NODES) {
                        const float2* p = (const float2*)(A + (size_t)gr * D_IN + nkb * 32) + a_q;
#pragma unroll
                        for (int j = 0; j < 4; j++) pf[rr][j] = p[j * 4];
                    } else {
#pragma unroll
                        for (int j = 0; j < 4; j++) pf[rr][j] = make_float2(0.f, 0.f);
                    }
                }
            }
            __syncthreads();

            // ---- compute: 2 k16 steps, LDS.64 fragment loads ----
#pragma unroll
            for (int kk = 0; kk < 2; kk++) {
                uint32_t ah[2][4], al[2][4];
#pragma unroll
                for (int mt = 0; mt < 2; mt++) {
                    const int r0 = warp_m * 32 + mt * 16 + g;
                    const uint32_t* b0 = as + r0 * AST + kk * 8 + 2 * c;
                    const uint32_t* b1 = as + (r0 + 8) * AST + kk * 8 + 2 * c;
                    uint2 h0 = *(const uint2*)b0;
                    uint2 h1 = *(const uint2*)b1;
                    uint2 l0 = *(const uint2*)(b0 + 16);
                    uint2 l1 = *(const uint2*)(b1 + 16);
                    ah[mt][0] = h0.x; ah[mt][2] = h0.y;
                    ah[mt][1] = h1.x; ah[mt][3] = h1.y;
                    al[mt][0] = l0.x; al[mt][2] = l0.y;
                    al[mt][1] = l1.x; al[mt][3] = l1.y;
                }
                uint32_t bh[4][2], bl[4][2];
#pragma unroll
                for (int nt = 0; nt < 4; nt++) {
                    const int n1 = warp_n * 32 + nt * 8 + g;
                    const uint32_t* wb = w_s + n1 * WS + kb * 16 + kk * 8 + 2 * c;
                    uint2 bv = *(const uint2*)wb;
                    uint2 lv = *(const uint2*)(wb + 128);
                    bh[nt][0] = bv.x; bh[nt][1] = bv.y;
                    bl[nt][0] = lv.x; bl[nt][1] = lv.y;
                }
#pragma unroll
                for (int mt = 0; mt < 2; mt++)
#pragma unroll
                    for (int nt = 0; nt < 4; nt++) {
                        mma16816(acc[mt][nt], ah[mt], bh[nt]);
                        mma16816(acc[mt][nt], al[mt], bh[nt]);
                        mma16816(acc[mt][nt], ah[mt], bl[nt]);
                    }
            }
        }

        // ---- epilogue: convert to fp16 (half2 per u32) ----
#pragma unroll
        for (int mt = 0; mt < 2; mt++) {
            const int r0 = m0 + warp_m * 32 + mt * 16 + g;
#pragma unroll
            for (int nt = 0; nt < 4; nt++) {
                const int u = half * 32 + warp_n * 16 + nt * 4 + c;   // u32 col
                if (r0 < N_NODES) {
                    __half2 h = __floats2half2_rn(acc[mt][nt][0], acc[mt][nt][1]);
                    g_support_h[(size_t)r0 * (D_OUT / 2) + u] = *(uint32_t*)&h;
                }
                if (r0 + 8 < N_NODES) {
                    __half2 h = __floats2half2_rn(acc[mt][nt][2], acc[mt][nt][3]);
                    g_support_h[(size_t)(r0 + 8) * (D_OUT / 2) + u] = *(uint32_t*)&h;
                }
            }
        }
        __syncthreads();
    }
}

// ---------------- 2) CSR build: histogram -> scan -> scatter -------------
__global__ void hist4_kernel(const int* __restrict__ rows) {
    int t = blockIdx.x * blockDim.x + threadIdx.x;
    if (t * 4 >= N_EDGES) return;
    int4 r = ((const int4*)rows)[t];
    atomicAdd(&g_counts[r.x], 1);
    atomicAdd(&g_counts[r.y], 1);
    atomicAdd(&g_counts[r.z], 1);
    atomicAdd(&g_counts[r.w], 1);
}

__global__ __launch_bounds__(SCAN_B)
void scan1_kernel() {
    __shared__ int sh[SCAN_B];
    int i = blockIdx.x * SCAN_B + threadIdx.x;
    int v = (i < N_NODES) ? g_counts[i] : 0;
    sh[threadIdx.x] = v;
    __syncthreads();
#pragma unroll
    for (int off = 1; off < SCAN_B; off <<= 1) {
        int t = (threadIdx.x >= off) ? sh[threadIdx.x - off] : 0;
        __syncthreads();
        sh[threadIdx.x] += t;
        __syncthreads();
    }
    if (i < N_NODES) g_rowptr[i] = sh[threadIdx.x] - v;   // block-local exclusive
    if (threadIdx.x == SCAN_B - 1) g_blocksums[blockIdx.x] = sh[SCAN_B - 1];
}

// merged scan2+scan3
__global__ __launch_bounds__(256)
void scan23_kernel() {
    __shared__ int sh[256];
    const int t = threadIdx.x;
    const int v = (t < NSB) ? g_blocksums[t] : 0;
    sh[t] = v;
    __syncthreads();
#pragma unroll
    for (int off = 1; off < 256; off <<= 1) {
        int x = (t >= off) ? sh[t - off] : 0;
        __syncthreads();
        sh[t] += x;
        __syncthreads();
    }
    __shared__ int base;
    if (t == 0) {
        const int seg = (blockIdx.x * 256) / SCAN_B;
        base = sh[seg] - g_blocksums[seg];
    }
    __syncthreads();
    const int i = blockIdx.x * 256 + t;
    if (i < N_NODES) {
        const int val = g_rowptr[i] + base;
        g_rowptr[i] = val;
        g_cursor[i] = val;
    }
    if (i == 0) g_rowptr[N_NODES] = N_EDGES;
}

__global__ void scatter4_kernel(const int* __restrict__ rows,
                                const int* __restrict__ cols,
                                const float* __restrict__ vals) {
    int t = blockIdx.x * blockDim.x + threadIdx.x;
    if (t * 4 >= N_EDGES) return;
    int4   r = ((const int4*)rows)[t];
    int4   c = ((const int4*)cols)[t];
    float4 v = ((const float4*)vals)[t];
    int p0 = atomicAdd(&g_cursor[r.x], 1);
    int p1 = atomicAdd(&g_cursor[r.y], 1);
    int p2 = atomicAdd(&g_cursor[r.z], 1);
    int p3 = atomicAdd(&g_cursor[r.w], 1);
    g_sorted_cv[p0] = make_int2(c.x, __float_as_int(v.x));
    g_sorted_cv[p1] = make_int2(c.y, __float_as_int(v.y));
    g_sorted_cv[p2] = make_int2(c.z, __float_as_int(v.z));
    g_sorted_cv[p3] = make_int2(c.w, __float_as_int(v.w));
}

// ---------------- 3) Aggregate: warp/row, shfl-broadcast edge data -------
__global__ __launch_bounds__(256)
void aggregate_kernel(const float* __restrict__ bias, float* __restrict__ out) {
    int w    = (blockIdx.x * blockDim.x + threadIdx.x) >> 5;   // row id
    int lane = threadIdx.x & 31;
    if (w >= N_NODES) return;

    const int s = g_rowptr[w];
    const int e = g_rowptr[w + 1];

    float4 acc = ((const float4*)bias)[lane];

    for (int base = s; base < e; base += 32) {
        const int rem = e - base;
        int2 cv = make_int2(0, 0);
        if (lane < rem) cv = g_sorted_cv[base + lane];    // one coalesced load
        const int n = rem < 32 ? rem : 32;

#pragma unroll 8
        for (int j = 0; j < n; j++) {
            const int   col = __shfl_sync(0xFFFFFFFFu, cv.x, j);
            const float v   = __int_as_float(__shfl_sync(0xFFFFFFFFu, cv.y, j));
            uint2 sv = *(const uint2*)&g_support_h[(size_t)col * 64 + lane * 2];
            float2 a = __half22float2(*(__half2*)&sv.x);
            float2 b = __half22float2(*(__half2*)&sv.y);
            acc.x += v * a.x; acc.y += v * a.y; acc.z += v * b.x; acc.w += v * b.y;
        }
    }

    *(float4*)&out[(size_t)w * D_OUT + lane * 4] = acc;
}

// ---------------- launch ------------------------------------------------
extern "C" void kernel_launch(void* const* d_in, const int* in_sizes, int n_in,
                              void* d_out, int out_size) {
    const float* in_feature = (const float*)d_in[0];   // [N, 256]
    const int*   edge_rows  = (const int*)d_in[1];     // [E]
    const int*   edge_cols  = (const int*)d_in[2];     // [E]
    const float* edge_vals  = (const float*)d_in[3];   // [E]
    const float* weight     = (const float*)d_in[4];   // [256, 128]
    const float* bias       = (const float*)d_in[5];   // [128]
    float*       out        = (float*)d_out;           // [N, 128]

    (void)in_sizes; (void)n_in; (void)out_size;

    static cudaStream_t s2 = 0;
    static cudaEvent_t ev_fork = 0, ev_join = 0;
    static void* counts_ptr = 0;
    static int init_done = 0;
    if (!init_done) {
        cudaFuncSetAttribute(gemm_mma_kernel, cudaFuncAttributeMaxDynamicSharedMemorySize, SM_TOTAL_B);
        cudaStreamCreateWithFlags(&s2, cudaStreamNonBlocking);
        cudaEventCreateWithFlags(&ev_fork, cudaEventDisableTiming);
        cudaEventCreateWithFlags(&ev_join, cudaEventDisableTiming);
        cudaGetSymbolAddress(&counts_ptr, g_counts);
        init_done = 1;
    }

    // fork: CSR build (s2) runs concurrently with GEMM (main stream)
    cudaEventRecord(ev_fork, 0);
    cudaStreamWaitEvent(s2, ev_fork, 0);

    // --- s2: CSR build front half ---
    cudaMemsetAsync(counts_ptr, 0, N_NODES * sizeof(int), s2);
    hist4_kernel<<<(N_EDGES / 4 + 255) / 256, 256, 0, s2>>>(edge_rows);
    scan1_kernel<<<NSB, SCAN_B, 0, s2>>>();
    scan23_kernel<<<(N_NODES + 255) / 256, 256, 0, s2>>>();

    // --- main stream: GEMM (ncu capture slot), 2 CTAs per 128-row tile ---
    gemm_mma_kernel<<<296, 256, SM_TOTAL_B>>>(in_feature, weight);

    // --- s2: CSR back half ---
    scatter4_kernel<<<(N_EDGES / 4 + 255) / 256, 256, 0, s2>>>(edge_rows, edge_cols, edge_vals);

    // join
    cudaEventRecord(ev_join, s2);
    cudaStreamWaitEvent(0, ev_join, 0);

    // 3) out = A @ support + bias   (one warp per row)
    int blocks = (N_NODES * 32 + 255) / 256;
    aggregate_kernel<<<blocks, 256>>>(bias, out);
}

// round 11
// speedup vs baseline: 1.1023x; 1.1023x over previous
#include <cuda_runtime.h>
#include <cuda_bf16.h>
#include <cuda_fp16.h>
#include <stdint.h>

#define N_NODES 100000
#define N_EDGES 1600000
#define D_IN    256
#define D_OUT   128
#define N_TILES ((N_NODES + 127) / 128)   // 782

// ---------------- device scratch (no allocations allowed) ----------------
// support stored as fp16, packed half2 in u32: [N_NODES][64] u32
__device__ uint32_t g_support_h[(size_t)N_NODES * (D_OUT / 2)];   // 25.6 MB
__device__ int   g_counts[N_NODES];
__device__ int   g_rowptr[N_NODES + 1];
__device__ int   g_cursor[N_NODES];
__device__ int2  g_sorted_cv[N_EDGES];                 // (col, val-bits) sorted by row

#define SCAN_B 1024
#define NSB    ((N_NODES + SCAN_B - 1) / SCAN_B)       // 98
__device__ int   g_blocksums[NSB];

// ---------------- 1) HMMA GEMM: support = X @ W (fp16 output) ------------
// Single CTA/SM, 512 threads, 128x128 tile.  k-pair-interleaved layouts:
// within each 16-pair (32-k) block, pair p (q=p&7, kk=p>>3) sits at
// pos = kk*8 + 2*(q&3) + (q>>2)  ->  MMA fragment pairs (c, c+4) ADJACENT
// -> LDS.64 fragment loads.  Strides: A 40 u32, W 264 u32 (both mod 32 = 8
// -> conflict-free per half-warp phase).
#define WS   264                           // per col: hi[0..127] lo[128..255] pad 8
#define AST  40                            // per row: hi[0..15] lo[16..31] pad 8
#define W_U32   (128 * WS)                 // 33792
#define A_U32S  (128 * AST)                // 5120
#define SM_TOTAL_B ((W_U32 + 2 * A_U32S) * 4)   // 176128 bytes

// pack two fp32 -> bf16x2 (f0 low half, f1 high half)
__device__ __forceinline__ uint32_t pack_bf(float f0, float f1) {
    uint32_t r;
    asm("cvt.rn.bf16x2.f32 %0, %1, %2;" : "=r"(r) : "f"(f1), "f"(f0));
    return r;
}
// residual pair for (f0, f1) vs packed hi hq
__device__ __forceinline__ uint32_t lo_bf(uint32_t hq, float f0, float f1) {
    float h0 = __uint_as_float(hq << 16);
    float h1 = __uint_as_float(hq & 0xFFFF0000u);
    return pack_bf(f0 - h0, f1 - h1);
}

__device__ __forceinline__ void mma16816(float* d, const uint32_t* a, const uint32_t* b) {
    asm volatile(
        "mma.sync.aligned.m16n8k16.row.col.f32.bf16.bf16.f32 "
        "{%0,%1,%2,%3}, {%4,%5,%6,%7}, {%8,%9}, {%0,%1,%2,%3};"
        : "+f"(d[0]), "+f"(d[1]), "+f"(d[2]), "+f"(d[3])
        : "r"(a[0]), "r"(a[1]), "r"(a[2]), "r"(a[3]), "r"(b[0]), "r"(b[1]));
}

__global__ __launch_bounds__(512, 1)
void gemm_mma_kernel(const float* __restrict__ A, const float* __restrict__ W) {
    extern __shared__ uint32_t smem[];
    uint32_t* w_s = smem;                  // [128][WS]
    uint32_t* a_s = smem + W_U32;          // [2][128][AST]

    const int tid    = threadIdx.x;
    const int wid    = tid >> 5;           // 0..15
    const int lane   = tid & 31;
    const int warp_m = wid & 3;            // 4 row-bands of 32
    const int warp_n = wid >> 2;           // 4 col-bands of 32
    const int g      = lane >> 2;
    const int c      = lane & 3;

    // ---- W prologue: split fp32 W -> bf16 hi/lo, interleaved, SMEM ----
    for (int idx = tid; idx < 128 * 128; idx += 512) {
        const int n = idx & 127;           // output col (MMA B n)
        const int p = idx >> 7;            // global k-pair 0..127
        const float w0 = W[(size_t)(2 * p) * D_OUT + n];
        const float w1 = W[(size_t)(2 * p + 1) * D_OUT + n];
        const uint32_t hq = pack_bf(w0, w1);
        const uint32_t lq = lo_bf(hq, w0, w1);
        const int q16 = p & 15, kk = q16 >> 3, q = q16 & 7;
        const int pos = (p >> 4) * 16 + kk * 8 + 2 * (q & 3) + (q >> 2);
        w_s[n * WS + pos]       = hq;
        w_s[n * WS + 128 + pos] = lq;
    }
    __syncthreads();

    // A loader: thread owns row a_row, pairs {a_q, a_q+4, a_q+8, a_q+12} of
    // each 16-pair block -> interleaved positions (2a_q,2a_q+1),(8+2a_q,..)
    const int a_row = tid >> 2;            // 0..127
    const int a_q   = tid & 3;

    // ---- register prefetch (depth 1): 4 float2 at pair-stride 4 ----
    float2 pf[4];
    {
        const int gr = blockIdx.x * 128 + a_row;
        if (blockIdx.x < N_TILES && gr < N_NODES) {
            const float2* p = (const float2*)(A + (size_t)gr * D_IN) + a_q;
#pragma unroll
            for (int j = 0; j < 4; j++) pf[j] = p[j * 4];
        } else {
#pragma unroll
            for (int j = 0; j < 4; j++) pf[j] = make_float2(0.f, 0.f);
        }
    }

    for (int tile = blockIdx.x; tile < N_TILES; tile += gridDim.x) {
        const int m0 = tile * 128;

        float acc[2][4][4];
#pragma unroll
        for (int mt = 0; mt < 2; mt++)
#pragma unroll
            for (int nt = 0; nt < 4; nt++)
#pragma unroll
                for (int q = 0; q < 4; q++) acc[mt][nt][q] = 0.f;

        for (int kb = 0; kb < 8; kb++) {
            const int st = kb & 1;
            uint32_t* as = a_s + st * A_U32S;

            // ---- convert prefetched regs + store interleaved (STS.64) ----
            {
                uint32_t hq[4], lq[4];
#pragma unroll
                for (int j = 0; j < 4; j++) {
                    hq[j] = pack_bf(pf[j].x, pf[j].y);
                    lq[j] = lo_bf(hq[j], pf[j].x, pf[j].y);
                }
                uint32_t* d = as + a_row * AST;
                *(uint2*)(d + 2 * a_q)          = make_uint2(hq[0], hq[1]);
                *(uint2*)(d + 8 + 2 * a_q)      = make_uint2(hq[2], hq[3]);
                *(uint2*)(d + 16 + 2 * a_q)     = make_uint2(lq[0], lq[1]);
                *(uint2*)(d + 16 + 8 + 2 * a_q) = make_uint2(lq[2], lq[3]);
            }

            // ---- issue prefetch for next k-block (or next tile) ----
            {
                int nkb = kb + 1, ntile = tile;
                if (nkb == 8) { nkb = 0; ntile = tile + gridDim.x; }
                const int gr = ntile * 128 + a_row;
                if (ntile < N_TILES && gr < N_NODES) {
                    const float2* p = (const float2*)(A + (size_t)gr * D_IN + nkb * 32) + a_q;
#pragma unroll
                    for (int j = 0; j < 4; j++) pf[j] = p[j * 4];
                } else {
#pragma unroll
                    for (int j = 0; j < 4; j++) pf[j] = make_float2(0.f, 0.f);
                }
            }
            __syncthreads();

            // ---- compute: 2 k16 steps, LDS.64 fragment loads ----
#pragma unroll
            for (int kk = 0; kk < 2; kk++) {
                uint32_t ah[2][4], al[2][4];
#pragma unroll
                for (int mt = 0; mt < 2; mt++) {
                    const int r0 = warp_m * 32 + mt * 16 + g;
                    const uint32_t* b0 = as + r0 * AST + kk * 8 + 2 * c;
                    const uint32_t* b1 = as + (r0 + 8) * AST + kk * 8 + 2 * c;
                    uint2 h0 = *(const uint2*)b0;
                    uint2 h1 = *(const uint2*)b1;
                    uint2 l0 = *(const uint2*)(b0 + 16);
                    uint2 l1 = *(const uint2*)(b1 + 16);
                    ah[mt][0] = h0.x; ah[mt][2] = h0.y;
                    ah[mt][1] = h1.x; ah[mt][3] = h1.y;
                    al[mt][0] = l0.x; al[mt][2] = l0.y;
                    al[mt][1] = l1.x; al[mt][3] = l1.y;
                }
                uint32_t bh[4][2], bl[4][2];
#pragma unroll
                for (int nt = 0; nt < 4; nt++) {
                    const int n = warp_n * 32 + nt * 8 + g;
                    const uint32_t* wb = w_s + n * WS + kb * 16 + kk * 8 + 2 * c;
                    uint2 bv = *(const uint2*)wb;
                    uint2 lv = *(const uint2*)(wb + 128);
                    bh[nt][0] = bv.x; bh[nt][1] = bv.y;
                    bl[nt][0] = lv.x; bl[nt][1] = lv.y;
                }
#pragma unroll
                for (int mt = 0; mt < 2; mt++)
#pragma unroll
                    for (int nt = 0; nt < 4; nt++) {
                        mma16816(acc[mt][nt], ah[mt], bh[nt]);
                        mma16816(acc[mt][nt], al[mt], bh[nt]);
                        mma16816(acc[mt][nt], ah[mt], bl[nt]);
                    }
            }
        }

        // ---- epilogue: convert to fp16 (half2 per u32) ----
#pragma unroll
        for (int mt = 0; mt < 2; mt++) {
            const int r0 = m0 + warp_m * 32 + mt * 16 + g;
#pragma unroll
            for (int nt = 0; nt < 4; nt++) {
                const int u = warp_n * 16 + nt * 4 + c;     // u32 col index
                if (r0 < N_NODES) {
                    __half2 h = __floats2half2_rn(acc[mt][nt][0], acc[mt][nt][1]);
                    g_support_h[(size_t)r0 * (D_OUT / 2) + u] = *(uint32_t*)&h;
                }
                if (r0 + 8 < N_NODES) {
                    __half2 h = __floats2half2_rn(acc[mt][nt][2], acc[mt][nt][3]);
                    g_support_h[(size_t)(r0 + 8) * (D_OUT / 2) + u] = *(uint32_t*)&h;
                }
            }
        }
        __syncthreads();
    }
}

// ---------------- 2) CSR build: histogram -> scan -> scatter -------------
__global__ void hist4_kernel(const int* __restrict__ rows) {
    int t = blockIdx.x * blockDim.x + threadIdx.x;
    if (t * 4 >= N_EDGES) return;
    int4 r = ((const int4*)rows)[t];
    atomicAdd(&g_counts[r.x], 1);
    atomicAdd(&g_counts[r.y], 1);
    atomicAdd(&g_counts[r.z], 1);
    atomicAdd(&g_counts[r.w], 1);
}

__global__ __launch_bounds__(SCAN_B)
void scan1_kernel() {
    __shared__ int sh[SCAN_B];
    int i = blockIdx.x * SCAN_B + threadIdx.x;
    int v = (i < N_NODES) ? g_counts[i] : 0;
    sh[threadIdx.x] = v;
    __syncthreads();
#pragma unroll
    for (int off = 1; off < SCAN_B; off <<= 1) {
        int t = (threadIdx.x >= off) ? sh[threadIdx.x - off] : 0;
        __syncthreads();
        sh[threadIdx.x] += t;
        __syncthreads();
    }
    if (i < N_NODES) g_rowptr[i] = sh[threadIdx.x] - v;   // block-local exclusive
    if (threadIdx.x == SCAN_B - 1) g_blocksums[blockIdx.x] = sh[SCAN_B - 1];
}

// merged scan2+scan3
__global__ __launch_bounds__(256)
void scan23_kernel() {
    __shared__ int sh[256];
    const int t = threadIdx.x;
    const int v = (t < NSB) ? g_blocksums[t] : 0;
    sh[t] = v;
    __syncthreads();
#pragma unroll
    for (int off = 1; off < 256; off <<= 1) {
        int x = (t >= off) ? sh[t - off] : 0;
        __syncthreads();
        sh[t] += x;
        __syncthreads();
    }
    __shared__ int base;
    if (t == 0) {
        const int seg = (blockIdx.x * 256) / SCAN_B;
        base = sh[seg] - g_blocksums[seg];
    }
    __syncthreads();
    const int i = blockIdx.x * 256 + t;
    if (i < N_NODES) {
        const int val = g_rowptr[i] + base;
        g_rowptr[i] = val;
        g_cursor[i] = val;
    }
    if (i == 0) g_rowptr[N_NODES] = N_EDGES;
}

__global__ void scatter4_kernel(const int* __restrict__ rows,
                                const int* __restrict__ cols,
                                const float* __restrict__ vals) {
    int t = blockIdx.x * blockDim.x + threadIdx.x;
    if (t * 4 >= N_EDGES) return;
    int4   r = ((const int4*)rows)[t];
    int4   c = ((const int4*)cols)[t];
    float4 v = ((const float4*)vals)[t];
    int p0 = atomicAdd(&g_cursor[r.x], 1);
    int p1 = atomicAdd(&g_cursor[r.y], 1);
    int p2 = atomicAdd(&g_cursor[r.z], 1);
    int p3 = atomicAdd(&g_cursor[r.w], 1);
    g_sorted_cv[p0] = make_int2(c.x, __float_as_int(v.x));
    g_sorted_cv[p1] = make_int2(c.y, __float_as_int(v.y));
    g_sorted_cv[p2] = make_int2(c.z, __float_as_int(v.z));
    g_sorted_cv[p3] = make_int2(c.w, __float_as_int(v.w));
}

// ---------------- 3) Aggregate: warp/row, shfl-broadcast edge data -------
__global__ __launch_bounds__(256)
void aggregate_kernel(const float* __restrict__ bias, float* __restrict__ out) {
    int w    = (blockIdx.x * blockDim.x + threadIdx.x) >> 5;   // row id
    int lane = threadIdx.x & 31;
    if (w >= N_NODES) return;

    const int s = g_rowptr[w];
    const int e = g_rowptr[w + 1];

    float4 acc = ((const float4*)bias)[lane];

    for (int base = s; base < e; base += 32) {
        const int rem = e - base;
        int2 cv = make_int2(0, 0);
        if (lane < rem) cv = g_sorted_cv[base + lane];    // one coalesced load
        const int n = rem < 32 ? rem : 32;

#pragma unroll 8
        for (int j = 0; j < n; j++) {
            const int   col = __shfl_sync(0xFFFFFFFFu, cv.x, j);
            const float v   = __int_as_float(__shfl_sync(0xFFFFFFFFu, cv.y, j));
            uint2 sv = *(const uint2*)&g_support_h[(size_t)col * 64 + lane * 2];
            float2 a = __half22float2(*(__half2*)&sv.x);
            float2 b = __half22float2(*(__half2*)&sv.y);
            acc.x += v * a.x; acc.y += v * a.y; acc.z += v * b.x; acc.w += v * b.y;
        }
    }

    *(float4*)&out[(size_t)w * D_OUT + lane * 4] = acc;
}

// ---------------- launch ------------------------------------------------
extern "C" void kernel_launch(void* const* d_in, const int* in_sizes, int n_in,
                              void* d_out, int out_size) {
    const float* in_feature = (const float*)d_in[0];   // [N, 256]
    const int*   edge_rows  = (const int*)d_in[1];     // [E]
    const int*   edge_cols  = (const int*)d_in[2];     // [E]
    const float* edge_vals  = (const float*)d_in[3];   // [E]
    const float* weight     = (const float*)d_in[4];   // [256, 128]
    const float* bias       = (const float*)d_in[5];   // [128]
    float*       out        = (float*)d_out;           // [N, 128]

    (void)in_sizes; (void)n_in; (void)out_size;

    static cudaStream_t s2 = 0;
    static cudaEvent_t ev_fork = 0, ev_join = 0;
    static void* counts_ptr = 0;
    static int init_done = 0;
    if (!init_done) {
        cudaFuncSetAttribute(gemm_mma_kernel, cudaFuncAttributeMaxDynamicSharedMemorySize, SM_TOTAL_B);
        cudaStreamCreateWithFlags(&s2, cudaStreamNonBlocking);
        cudaEventCreateWithFlags(&ev_fork, cudaEventDisableTiming);
        cudaEventCreateWithFlags(&ev_join, cudaEventDisableTiming);
        cudaGetSymbolAddress(&counts_ptr, g_counts);
        init_done = 1;
    }

    // fork: CSR build (s2) runs concurrently with GEMM (main stream)
    cudaEventRecord(ev_fork, 0);
    cudaStreamWaitEvent(s2, ev_fork, 0);

    // --- s2: CSR build front half ---
    cudaMemsetAsync(counts_ptr, 0, N_NODES * sizeof(int), s2);
    hist4_kernel<<<(N_EDGES / 4 + 255) / 256, 256, 0, s2>>>(edge_rows);
    scan1_kernel<<<NSB, SCAN_B, 0, s2>>>();
    scan23_kernel<<<(N_NODES + 255) / 256, 256, 0, s2>>>();

    // --- main stream: GEMM (ncu capture slot) ---
    gemm_mma_kernel<<<148, 512, SM_TOTAL_B>>>(in_feature, weight);

    // --- s2: CSR back half ---
    scatter4_kernel<<<(N_EDGES / 4 + 255) / 256, 256, 0, s2>>>(edge_rows, edge_cols, edge_vals);

    // join
    cudaEventRecord(ev_join, s2);
    cudaStreamWaitEvent(0, ev_join, 0);

    // 3) out = A @ support + bias   (one warp per row)
    int blocks = (N_NODES * 32 + 255) / 256;
    aggregate_kernel<<<blocks, 256>>>(bias, out);
}

// round 12
// speedup vs baseline: 1.3174x; 1.1952x over previous
#include <cuda_runtime.h>
#include <cuda_bf16.h>
#include <cuda_fp16.h>
#include <stdint.h>

#define N_NODES 100000
#define N_EDGES 1600000
#define D_IN    256
#define D_OUT   128
#define N_TILES ((N_NODES + 127) / 128)   // 782

// ---------------- device scratch (no allocations allowed) ----------------
// support stored as fp16, packed half2 in u32: [N_NODES][64] u32
__device__ uint32_t g_support_h[(size_t)N_NODES * (D_OUT / 2)];   // 25.6 MB
__device__ int   g_counts[N_NODES];
__device__ int   g_rowptr[N_NODES + 1];
__device__ int   g_cursor[N_NODES];
__device__ int2  g_sorted_cv[N_EDGES];                 // (col, val-bits) sorted by row

#define SCAN_B 1024
#define NSB    ((N_NODES + SCAN_B - 1) / SCAN_B)       // 98
__device__ int   g_blocksums[NSB];

// ---------------- 1) fp16 HMMA GEMM: support = X @ W ---------------------
// Single pass, fp16 inputs, fp32 accum.  R8-proven layout:
//   W: u32[n*132 + k/2]  (fp16 pair per u32), resident in SMEM
//   A: 2 stages x 128 rows x 20 u32
#define WSTRIDE 132
#define ASTRIDE 20
#define W_U32   (128 * WSTRIDE)            // 16896
#define A_U32S  (128 * ASTRIDE)            // 2560
#define SM_TOTAL_B ((W_U32 + 2 * A_U32S) * 4)   // 88064 bytes

// pack two fp32 -> fp16x2 (f0 low half, f1 high half)
__device__ __forceinline__ uint32_t pack_h2(float f0, float f1) {
    uint32_t r;
    asm("cvt.rn.f16x2.f32 %0, %1, %2;" : "=r"(r) : "f"(f1), "f"(f0));
    return r;
}

__device__ __forceinline__ void mma_f16(float* d, const uint32_t* a, const uint32_t* b) {
    asm volatile(
        "mma.sync.aligned.m16n8k16.row.col.f32.f16.f16.f32 "
        "{%0,%1,%2,%3}, {%4,%5,%6,%7}, {%8,%9}, {%0,%1,%2,%3};"
        : "+f"(d[0]), "+f"(d[1]), "+f"(d[2]), "+f"(d[3])
        : "r"(a[0]), "r"(a[1]), "r"(a[2]), "r"(a[3]), "r"(b[0]), "r"(b[1]));
}

__global__ __launch_bounds__(512, 1)
void gemm_mma_kernel(const float* __restrict__ A, const float* __restrict__ W) {
    extern __shared__ uint32_t smem[];
    uint32_t* w_s   = smem;                // [128][WSTRIDE]
    uint32_t* a_buf = smem + W_U32;        // [2 stages][A_U32S]

    const int tid    = threadIdx.x;
    const int wid    = tid >> 5;           // 0..15
    const int lane   = tid & 31;
    const int warp_m = wid & 3;            // 4 row-bands of 32
    const int warp_n = wid >> 2;           // 4 col-bands of 32
    const int g      = lane >> 2;          // groupID
    const int c      = lane & 3;           // threadID_in_group

    // ---- W prologue: fp32 -> fp16 pairs into SMEM ----
    for (int idx = tid; idx < D_IN * D_OUT; idx += 512) {
        const int n = idx & 127;           // output col (MMA B n)
        const int k = idx >> 7;            // input dim (K)
        __half h = __float2half_rn(W[(size_t)k * D_OUT + n]);
        ((uint16_t*)&w_s[n * WSTRIDE + (k >> 1)])[k & 1] = *(uint16_t*)&h;
    }
    __syncthreads();

    const int a_row = tid >> 2;            // 0..127
    const int a_q   = tid & 3;             // 8-float quarter of the 32-k block

    // ---- register prefetch of the A block (software pipeline) ----
    float4 p0, p1;
    {
        const int gr = blockIdx.x * 128 + a_row;
        if (blockIdx.x < N_TILES && gr < N_NODES) {
            const float4* p = (const float4*)(A + (size_t)gr * D_IN + a_q * 8);
            p0 = p[0]; p1 = p[1];
        } else {
            p0 = p1 = make_float4(0.f, 0.f, 0.f, 0.f);
        }
    }

    for (int tile = blockIdx.x; tile < N_TILES; tile += gridDim.x) {
        const int m0 = tile * 128;

        float acc[2][4][4];
#pragma unroll
        for (int mt = 0; mt < 2; mt++)
#pragma unroll
            for (int nt = 0; nt < 4; nt++)
#pragma unroll
                for (int q = 0; q < 4; q++) acc[mt][nt][q] = 0.f;

        for (int kb = 0; kb < 8; kb++) {           // K blocks of 32
            const int st = kb & 1;
            uint32_t* as = a_buf + st * A_U32S;

            // ---- convert prefetched regs to fp16 pairs + store to stage ----
            {
                uint4 t = make_uint4(pack_h2(p0.x, p0.y), pack_h2(p0.z, p0.w),
                                     pack_h2(p1.x, p1.y), pack_h2(p1.z, p1.w));
                *(uint4*)(as + a_row * ASTRIDE + a_q * 4) = t;
            }

            // ---- issue prefetch for next k-block (or next tile) ----
            {
                int nkb = kb + 1, ntile = tile;
                if (nkb == 8) { nkb = 0; ntile = tile + gridDim.x; }
                const int gr = ntile * 128 + a_row;
                if (ntile < N_TILES && gr < N_NODES) {
                    const float4* p = (const float4*)(A + (size_t)gr * D_IN + nkb * 32 + a_q * 8);
                    p0 = p[0]; p1 = p[1];
                } else {
                    p0 = p1 = make_float4(0.f, 0.f, 0.f, 0.f);
                }
            }
            __syncthreads();

            // ---- compute: 2 k16 steps ----
#pragma unroll
            for (int kk = 0; kk < 2; kk++) {
                const int kpl = kk * 8 + c;                 // local kpair for A
                const int kpg = kb * 16 + kk * 8 + c;       // global kpair for W

                uint32_t av[2][4];
#pragma unroll
                for (int mt = 0; mt < 2; mt++) {
                    const int r0 = (warp_m * 32 + mt * 16 + g) * ASTRIDE;
                    const int r1 = r0 + 8 * ASTRIDE;
                    av[mt][0] = as[r0 + kpl];
                    av[mt][1] = as[r1 + kpl];
                    av[mt][2] = as[r0 + kpl + 4];
                    av[mt][3] = as[r1 + kpl + 4];
                }
                uint32_t bv[4][2];
#pragma unroll
                for (int nt = 0; nt < 4; nt++) {
                    const int n = warp_n * 32 + nt * 8 + g;
                    bv[nt][0] = w_s[n * WSTRIDE + kpg];
                    bv[nt][1] = w_s[n * WSTRIDE + kpg + 4];
                }
#pragma unroll
                for (int mt = 0; mt < 2; mt++)
#pragma unroll
                    for (int nt = 0; nt < 4; nt++)
                        mma_f16(acc[mt][nt], av[mt], bv[nt]);
            }
        }

        // ---- epilogue: convert to fp16 (half2 per u32) ----
#pragma unroll
        for (int mt = 0; mt < 2; mt++) {
            const int r0 = m0 + warp_m * 32 + mt * 16 + g;
#pragma unroll
            for (int nt = 0; nt < 4; nt++) {
                const int u = warp_n * 16 + nt * 4 + c;     // u32 col index
                if (r0 < N_NODES) {
                    __half2 h = __floats2half2_rn(acc[mt][nt][0], acc[mt][nt][1]);
                    g_support_h[(size_t)r0 * (D_OUT / 2) + u] = *(uint32_t*)&h;
                }
                if (r0 + 8 < N_NODES) {
                    __half2 h = __floats2half2_rn(acc[mt][nt][2], acc[mt][nt][3]);
                    g_support_h[(size_t)(r0 + 8) * (D_OUT / 2) + u] = *(uint32_t*)&h;
                }
            }
        }
        __syncthreads();
    }
}

// ---------------- 2) CSR build: histogram -> scan -> scatter -------------
__global__ void hist4_kernel(const int* __restrict__ rows) {
    int t = blockIdx.x * blockDim.x + threadIdx.x;
    if (t * 4 >= N_EDGES) return;
    int4 r = ((const int4*)rows)[t];
    atomicAdd(&g_counts[r.x], 1);
    atomicAdd(&g_counts[r.y], 1);
    atomicAdd(&g_counts[r.z], 1);
    atomicAdd(&g_counts[r.w], 1);
}

__global__ __launch_bounds__(SCAN_B)
void scan1_kernel() {
    __shared__ int sh[SCAN_B];
    int i = blockIdx.x * SCAN_B + threadIdx.x;
    int v = (i < N_NODES) ? g_counts[i] : 0;
    sh[threadIdx.x] = v;
    __syncthreads();
#pragma unroll
    for (int off = 1; off < SCAN_B; off <<= 1) {
        int t = (threadIdx.x >= off) ? sh[threadIdx.x - off] : 0;
        __syncthreads();
        sh[threadIdx.x] += t;
        __syncthreads();
    }
    if (i < N_NODES) g_rowptr[i] = sh[threadIdx.x] - v;   // block-local exclusive
    if (threadIdx.x == SCAN_B - 1) g_blocksums[blockIdx.x] = sh[SCAN_B - 1];
}

// merged scan2+scan3
__global__ __launch_bounds__(256)
void scan23_kernel() {
    __shared__ int sh[256];
    const int t = threadIdx.x;
    const int v = (t < NSB) ? g_blocksums[t] : 0;
    sh[t] = v;
    __syncthreads();
#pragma unroll
    for (int off = 1; off < 256; off <<= 1) {
        int x = (t >= off) ? sh[t - off] : 0;
        __syncthreads();
        sh[t] += x;
        __syncthreads();
    }
    __shared__ int base;
    if (t == 0) {
        const int seg = (blockIdx.x * 256) / SCAN_B;
        base = sh[seg] - g_blocksums[seg];
    }
    __syncthreads();
    const int i = blockIdx.x * 256 + t;
    if (i < N_NODES) {
        const int val = g_rowptr[i] + base;
        g_rowptr[i] = val;
        g_cursor[i] = val;
    }
    if (i == 0) g_rowptr[N_NODES] = N_EDGES;
}

__global__ void scatter4_kernel(const int* __restrict__ rows,
                                const int* __restrict__ cols,
                                const float* __restrict__ vals) {
    int t = blockIdx.x * blockDim.x + threadIdx.x;
    if (t * 4 >= N_EDGES) return;
    int4   r = ((const int4*)rows)[t];
    int4   c = ((const int4*)cols)[t];
    float4 v = ((const float4*)vals)[t];
    int p0 = atomicAdd(&g_cursor[r.x], 1);
    int p1 = atomicAdd(&g_cursor[r.y], 1);
    int p2 = atomicAdd(&g_cursor[r.z], 1);
    int p3 = atomicAdd(&g_cursor[r.w], 1);
    g_sorted_cv[p0] = make_int2(c.x, __float_as_int(v.x));
    g_sorted_cv[p1] = make_int2(c.y, __float_as_int(v.y));
    g_sorted_cv[p2] = make_int2(c.z, __float_as_int(v.z));
    g_sorted_cv[p3] = make_int2(c.w, __float_as_int(v.w));
}

// ---------------- 3) Aggregate: warp/row, shfl-broadcast edge data -------
__global__ __launch_bounds__(256)
void aggregate_kernel(const float* __restrict__ bias, float* __restrict__ out) {
    int w    = (blockIdx.x * blockDim.x + threadIdx.x) >> 5;   // row id
    int lane = threadIdx.x & 31;
    if (w >= N_NODES) return;

    const int s = g_rowptr[w];
    const int e = g_rowptr[w + 1];

    float4 acc = ((const float4*)bias)[lane];

    for (int base = s; base < e; base += 32) {
        const int rem = e - base;
        int2 cv = make_int2(0, 0);
        if (lane < rem) cv = g_sorted_cv[base + lane];    // one coalesced load
        const int n = rem < 32 ? rem : 32;

#pragma unroll 8
        for (int j = 0; j < n; j++) {
            const int   col = __shfl_sync(0xFFFFFFFFu, cv.x, j);
            const float v   = __int_as_float(__shfl_sync(0xFFFFFFFFu, cv.y, j));
            uint2 sv = *(const uint2*)&g_support_h[(size_t)col * 64 + lane * 2];
            float2 a = __half22float2(*(__half2*)&sv.x);
            float2 b = __half22float2(*(__half2*)&sv.y);
            acc.x += v * a.x; acc.y += v * a.y; acc.z += v * b.x; acc.w += v * b.y;
        }
    }

    *(float4*)&out[(size_t)w * D_OUT + lane * 4] = acc;
}

// ---------------- launch ------------------------------------------------
extern "C" void kernel_launch(void* const* d_in, const int* in_sizes, int n_in,
                              void* d_out, int out_size) {
    const float* in_feature = (const float*)d_in[0];   // [N, 256]
    const int*   edge_rows  = (const int*)d_in[1];     // [E]
    const int*   edge_cols  = (const int*)d_in[2];     // [E]
    const float* edge_vals  = (const float*)d_in[3];   // [E]
    const float* weight     = (const float*)d_in[4];   // [256, 128]
    const float* bias       = (const float*)d_in[5];   // [128]
    float*       out        = (float*)d_out;           // [N, 128]

    (void)in_sizes; (void)n_in; (void)out_size;

    static cudaStream_t s2 = 0;
    static cudaEvent_t ev_fork = 0, ev_join = 0;
    static void* counts_ptr = 0;
    static int init_done = 0;
    if (!init_done) {
        cudaFuncSetAttribute(gemm_mma_kernel, cudaFuncAttributeMaxDynamicSharedMemorySize, SM_TOTAL_B);
        cudaStreamCreateWithFlags(&s2, cudaStreamNonBlocking);
        cudaEventCreateWithFlags(&ev_fork, cudaEventDisableTiming);
        cudaEventCreateWithFlags(&ev_join, cudaEventDisableTiming);
        cudaGetSymbolAddress(&counts_ptr, g_counts);
        init_done = 1;
    }

    // fork: CSR build (s2) runs concurrently with GEMM (main stream)
    cudaEventRecord(ev_fork, 0);
    cudaStreamWaitEvent(s2, ev_fork, 0);

    // --- s2: CSR build front half ---
    cudaMemsetAsync(counts_ptr, 0, N_NODES * sizeof(int), s2);
    hist4_kernel<<<(N_EDGES / 4 + 255) / 256, 256, 0, s2>>>(edge_rows);
    scan1_kernel<<<NSB, SCAN_B, 0, s2>>>();
    scan23_kernel<<<(N_NODES + 255) / 256, 256, 0, s2>>>();

    // --- main stream: GEMM (ncu capture slot) ---
    gemm_mma_kernel<<<148, 512, SM_TOTAL_B>>>(in_feature, weight);

    // --- s2: CSR back half ---
    scatter4_kernel<<<(N_EDGES / 4 + 255) / 256, 256, 0, s2>>>(edge_rows, edge_cols, edge_vals);

    // join
    cudaEventRecord(ev_join, s2);
    cudaStreamWaitEvent(0, ev_join, 0);

    // 3) out = A @ support + bias   (one warp per row)
    int blocks = (N_NODES * 32 + 255) / 256;
    aggregate_kernel<<<blocks, 256>>>(bias, out);
}